// round 6
// baseline (speedup 1.0000x reference)
#include <cuda_runtime.h>
#include <math.h>

// Problem constants (fixed by setup_inputs)
#define B_    2
#define M_    384
#define N_    384
// C_IN=8, C_OUT=8 -> 16 feature comps (i,x), 16 output comps (o,y)
// Table: H=10 (theta, wrapped), W=4 (radius) -> 40 cells

// Shared-memory layout (float offsets)
#define OFF_FEAT   0        // 384*16 = 6144
#define OFF_FIELD  6144     // 384*2  = 768
#define OFF_MASK   6912     // 384
#define OFF_GATT   7296     // 384
#define OFF_GWX    7680     // 384
#define OFF_GWY    8064     // 384
#define OFF_GXY    8448     // 384 (int)
#define OFF_S      8832     // 16 copies * 640 = 10240
#define OFF_STOT   19072    // 640
#define OFF_KTAB   19712    // 4*8*16*16 = 8192
#define OFF_RED    27904    // 256
#define OFF_PSI    28160    // 4 (padded)
#define SMEM_FLOATS 28164
#define SMEM_BYTES  (SMEM_FLOATS * 4)

__global__ __launch_bounds__(256, 2)
void equi_cts_conv_kernel(const float* __restrict__ field,
                          const float* __restrict__ center,
                          const float* __restrict__ feat,
                          const float* __restrict__ mask,
                          const float* __restrict__ kern,
                          float* __restrict__ out)
{
    extern __shared__ float sm[];
    float* feat_s  = sm + OFF_FEAT;
    float* field_s = sm + OFF_FIELD;
    float* mask_s  = sm + OFF_MASK;
    float* g_att   = sm + OFF_GATT;
    float* g_wx    = sm + OFF_GWX;
    float* g_wy    = sm + OFF_GWY;
    int*   g_xy    = (int*)(sm + OFF_GXY);
    float* S       = sm + OFF_S;
    float* Stot    = sm + OFF_STOT;
    float* ktab    = sm + OFF_KTAB;
    float* red     = sm + OFF_RED;
    float* shpsi   = sm + OFF_PSI;

    const int tid = threadIdx.x;
    const int bm  = blockIdx.x;
    const int b   = bm / M_;

    const float cx = center[bm * 2 + 0];
    const float cy = center[bm * 2 + 1];

    // ---------- Phase 0: stage inputs ----------
    {
        const float4* featB = (const float4*)(feat + (size_t)b * N_ * 16);
        float4* f4s = (float4*)feat_s;
        #pragma unroll
        for (int i = tid; i < N_ * 4; i += 256) f4s[i] = featB[i];

        const float* fB = field + (size_t)b * N_ * 2;
        for (int i = tid; i < N_ * 2; i += 256) field_s[i] = fB[i];

        const float* mB = mask + (size_t)b * N_;
        for (int i = tid; i < N_; i += 256) mask_s[i] = mB[i];

        // ktab[w(4)][t(8)][comp(16)][oy(16)] <- kern[o][i][r=w][t][y][x]  (8192 entries)
        for (int d = tid; d < 8192; d += 256) {
            int oy   = d & 15;
            int comp = (d >> 4) & 15;
            int t    = (d >> 8) & 7;
            int w    = d >> 11;              // 0..3
            int o = oy >> 1, y = oy & 1;
            int ii = comp >> 1, x = comp & 1;
            ktab[d] = kern[o * 1024 + ii * 128 + w * 32 + t * 4 + y * 2 + x];
        }

        float4 z = make_float4(0.f, 0.f, 0.f, 0.f);
        float4* S4 = (float4*)S;
        #pragma unroll
        for (int i = tid; i < 2560; i += 256) S4[i] = z;
    }
    __syncthreads();

    // ---------- Phase A: per-n geometry (deduplicated) ----------
    float psi_part = 0.f;
    for (int n = tid; n < N_; n += 256) {
        float relx = (field_s[2 * n]     - cx) * (1.0f / 1.5f);
        float rely = (field_s[2 * n + 1] - cy) * (1.0f / 1.5f);
        float r2 = relx * relx + rely * rely;
        float s  = 1.0f - r2;
        float att = 0.f, wx = 0.f, wy = 0.f;
        int xy = 0;
        if (s > 0.0f) {
            att = s * s * s * mask_s[n];
            float r = sqrtf(r2 + 1e-9f);
            float theta = (relx == 0.0f && rely == 0.0f) ? 0.0f : atan2f(rely, relx);
            float ix = 4.0f * r - 0.5f;                       // ((gx+1)*W-1)/2, gx=2r-1, W=4
            float gy = theta * 0.318309886183790672f * 0.8f;  // theta/pi * 8/10
            float iy = fmaf(5.0f, gy, 4.5f);                  // ((gy+1)*H-1)/2, H=10
            float x0f = floorf(ix), y0f = floorf(iy);
            wx = ix - x0f;
            wy = iy - y0f;
            int x0 = (int)x0f, y0 = (int)y0f;                 // x0 in [-1,3], y0 in [0,8]
            xy = (x0 + 1) | (y0 << 4);
            psi_part += att;
        }
        g_att[n] = att; g_wx[n] = wx; g_wy[n] = wy; g_xy[n] = xy;
    }

    // psi block-reduce (warp shfl -> 8 partials -> thread 0)
    #pragma unroll
    for (int o = 16; o; o >>= 1) psi_part += __shfl_xor_sync(0xffffffffu, psi_part, o);
    if ((tid & 31) == 0) red[tid >> 5] = psi_part;
    __syncthreads();
    if (tid == 0) {
        float p = 0.f;
        #pragma unroll
        for (int w = 0; w < 8; ++w) p += red[w];
        shpsi[0] = (p == 0.0f) ? 1.0f : p;
    }

    // ---------- Phase B: scatter into per-half-warp S copies ----------
    {
        const int lane   = tid & 31;
        const int warp   = tid >> 5;
        const int sub    = lane >> 4;       // which n of this warp's pair
        const int h16    = lane & 15;
        const int corner = h16 >> 2;        // 0..3
        const int quad   = h16 & 3;         // float4 slice of the 16 comps
        const int cbx    = corner & 1;
        const int cby    = corner >> 1;
        float* Smine = S + (warp * 2 + sub) * 640;
        const int nbase = warp * 2 + sub;
        const float4* f4s = (const float4*)feat_s;

        #pragma unroll 4
        for (int it = 0; it < N_ / 16; ++it) {
            int n = it * 16 + nbase;
            float att = g_att[n];
            if (att != 0.0f) {
                float wx = g_wx[n], wy = g_wy[n];
                int xy = g_xy[n];
                int xi = (xy & 15) - 1 + cbx;
                int yi = (xy >> 4) + cby;
                if (xi >= 0 && xi <= 3 && (unsigned)yi <= 9u) {
                    float wcx = cbx ? wx : 1.0f - wx;
                    float wcy = cby ? wy : 1.0f - wy;
                    float A = att * wcx * wcy;
                    float4 f = f4s[n * 4 + quad];
                    float4* sp = (float4*)(Smine + (yi * 4 + xi) * 16 + quad * 4);
                    float4 sv = *sp;
                    sv.x = fmaf(A, f.x, sv.x);
                    sv.y = fmaf(A, f.y, sv.y);
                    sv.z = fmaf(A, f.z, sv.z);
                    sv.w = fmaf(A, f.w, sv.w);
                    *sp = sv;
                }
            }
            __syncwarp();   // order cross-lane shared RMW between iterations
        }
    }
    __syncthreads();

    // ---------- Phase C1: reduce 16 S copies ----------
    for (int e = tid; e < 640; e += 256) {
        float a = 0.f;
        #pragma unroll
        for (int c = 0; c < 16; ++c) a += S[c * 640 + e];
        Stot[e] = a;
    }
    __syncthreads();

    // ---------- Phase C2: final contraction out[o,y] = sum_{cell,comp} ktab * Stot ----------
    {
        int oy = tid & 15;   // (o,y)
        int g  = tid >> 4;   // comp handled by this group
        float acc = 0.f;
        #pragma unroll
        for (int j = 0; j < 40; ++j) {       // cell = h*4+w
            int h = j >> 2, w = j & 3;
            int t = (h + 7) & 7;             // theta wrap of padded table
            acc = fmaf(ktab[((w * 8 + t) * 16 + g) * 16 + oy], Stot[j * 16 + g], acc);
        }
        red[tid] = acc;
    }
    __syncthreads();

    if (tid < 16) {
        float ssum = 0.f;
        #pragma unroll
        for (int g2 = 0; g2 < 16; ++g2) ssum += red[g2 * 16 + tid];
        out[bm * 16 + tid] = ssum / shpsi[0];
    }
}

extern "C" void kernel_launch(void* const* d_in, const int* in_sizes, int n_in,
                              void* d_out, int out_size)
{
    const float* field  = (const float*)d_in[0];
    const float* center = (const float*)d_in[1];
    const float* feat   = (const float*)d_in[2];
    const float* mask   = (const float*)d_in[3];
    const float* kern   = (const float*)d_in[4];
    float* out = (float*)d_out;

    cudaFuncSetAttribute(equi_cts_conv_kernel,
                         cudaFuncAttributeMaxDynamicSharedMemorySize, SMEM_BYTES);
    equi_cts_conv_kernel<<<B_ * M_, 256, SMEM_BYTES>>>(field, center, feat, mask, kern, out);
}

// round 8
// speedup vs baseline: 1.3840x; 1.3840x over previous
#include <cuda_runtime.h>
#include <math.h>

#define B_ 2
#define M_ 384
#define N_ 384

// Shared-memory layout (float offsets)
#define OFF_FEAT  0        // 384*16 = 6144
#define OFF_CATT  6144     // 384 (compacted att)
#define OFF_CWX   6528     // 384
#define OFF_CWY   6912     // 384
#define OFF_CNXY  7296     // 384 (int: n<<8 | (y0<<4) | (x0+1))
#define OFF_S     7680     // 8 copies * 640 = 5120
#define OFF_STOT  12800    // 640
#define OFF_SFOLD 13440    // 512  [w(4)][t(8)][comp(16)]
#define OFF_RED   13952    // 8 (psi warp partials)
#define OFF_PSI   13960    // 1
#define OFF_PAD   13961
#define SMEM_FLOATS 13964
#define SMEM_BYTES  (SMEM_FLOATS * 4)   // 55856 B -> 4 blocks/SM

__global__ __launch_bounds__(256, 4)
void equi_cts_conv_kernel(const float* __restrict__ field,
                          const float* __restrict__ center,
                          const float* __restrict__ feat,
                          const float* __restrict__ mask,
                          const float* __restrict__ kern,
                          float* __restrict__ out)
{
    extern __shared__ float sm[];
    float* feat_s = sm + OFF_FEAT;
    float* catt   = sm + OFF_CATT;
    float* cwx    = sm + OFF_CWX;
    float* cwy    = sm + OFF_CWY;
    int*   cnxy   = (int*)(sm + OFF_CNXY);
    float* S      = sm + OFF_S;
    float* Stot   = sm + OFF_STOT;
    float* Sfold  = sm + OFF_SFOLD;
    float* red    = sm + OFF_RED;
    float* shpsi  = sm + OFF_PSI;
    __shared__ int wcnt[16];   // per (round, warp) active counts

    const int tid  = threadIdx.x;
    const int lane = tid & 31;
    const int warp = tid >> 5;
    const int bm   = blockIdx.x;
    const int b    = bm / M_;

    const float cx = center[bm * 2 + 0];
    const float cy = center[bm * 2 + 1];

    // ---------- Phase 0: stage feat, zero S ----------
    {
        const float4* featB = (const float4*)(feat + (size_t)b * N_ * 16);
        float4* f4s = (float4*)feat_s;
        #pragma unroll
        for (int i = tid; i < N_ * 4; i += 256) f4s[i] = featB[i];

        float4 z = make_float4(0.f, 0.f, 0.f, 0.f);
        float4* S4 = (float4*)S;
        #pragma unroll
        for (int i = tid; i < 1280; i += 256) S4[i] = z;
    }

    // ---------- Phase A1: geometry + ballots (field/mask straight from L2) ----------
    float psi_part = 0.f;
    unsigned ballots[2];
    float a_att[2], a_wx[2], a_wy[2];
    int   a_pk[2];
    bool  a_act[2];
    #pragma unroll
    for (int r = 0; r < 2; ++r) {
        int n = r * 256 + tid;
        bool act = false;
        float att = 0.f, wxv = 0.f, wyv = 0.f;
        int pack = 0;
        if (n < N_) {
            float2 fp = *(const float2*)(field + ((size_t)b * N_ + n) * 2);
            float relx = (fp.x - cx) * (1.0f / 1.5f);
            float rely = (fp.y - cy) * (1.0f / 1.5f);
            float r2 = relx * relx + rely * rely;
            float s  = 1.0f - r2;
            if (s > 0.0f) {
                att = s * s * s * mask[(size_t)b * N_ + n];
                float rr = sqrtf(r2 + 1e-9f);
                float theta = (relx == 0.0f && rely == 0.0f) ? 0.0f : atan2f(rely, relx);
                float ix = 4.0f * rr - 0.5f;                      // ((gx+1)*W-1)/2, W=4
                float gy = theta * 0.318309886183790672f * 0.8f;  // theta/pi * 8/10
                float iy = fmaf(5.0f, gy, 4.5f);                  // H=10
                float x0f = floorf(ix), y0f = floorf(iy);
                wxv = ix - x0f;
                wyv = iy - y0f;
                int x0 = (int)x0f, y0 = (int)y0f;                 // x0 in [-1,3], y0 in [0,8]
                pack = ((x0 + 1) | (y0 << 4)) | (n << 8);
                psi_part += att;
                act = (att != 0.0f);
            }
        }
        a_att[r] = att; a_wx[r] = wxv; a_wy[r] = wyv; a_pk[r] = pack; a_act[r] = act;
        ballots[r] = __ballot_sync(0xffffffffu, act);
        if (lane == 0) wcnt[r * 8 + warp] = __popc(ballots[r]);
    }

    // psi warp-reduce
    #pragma unroll
    for (int o = 16; o; o >>= 1) psi_part += __shfl_xor_sync(0xffffffffu, psi_part, o);
    if (lane == 0) red[warp] = psi_part;
    __syncthreads();   // covers Phase 0 staging, wcnt, red

    // ---------- Phase A2: deterministic prefix + compacted write ----------
    int nact;
    {
        int tot = 0, base0 = 0, base1 = 0;
        #pragma unroll
        for (int s2 = 0; s2 < 16; ++s2) {
            if (s2 == warp)     base0 = tot;
            if (s2 == warp + 8) base1 = tot;
            tot += wcnt[s2];
        }
        nact = tot;
        unsigned lt = (1u << lane) - 1u;
        if (a_act[0]) {
            int idx = base0 + __popc(ballots[0] & lt);
            catt[idx] = a_att[0]; cwx[idx] = a_wx[0]; cwy[idx] = a_wy[0]; cnxy[idx] = a_pk[0];
        }
        if (a_act[1]) {
            int idx = base1 + __popc(ballots[1] & lt);
            catt[idx] = a_att[1]; cwx[idx] = a_wx[1]; cwy[idx] = a_wy[1]; cnxy[idx] = a_pk[1];
        }
        if (tid == 0) {
            float p = 0.f;
            #pragma unroll
            for (int w = 0; w < 8; ++w) p += red[w];
            shpsi[0] = (p == 0.0f) ? 1.0f : p;
        }
    }
    __syncthreads();

    // ---------- Phase B: scatter, one n per warp-iter, 32 lanes = 4 corners x 8 float2 ----------
    {
        const int corner = lane >> 3;       // 0..3
        const int pairi  = lane & 7;        // comp pair (float2)
        const int cbx = corner & 1;
        const int cby = corner >> 1;
        float* Smine = S + warp * 640;

        for (int k = warp; k < nact; k += 8) {
            float att = catt[k], wxv = cwx[k], wyv = cwy[k];
            int pk = cnxy[k];
            int n  = pk >> 8;
            int xi = (pk & 15) - 1 + cbx;
            int yi = ((pk >> 4) & 15) + cby;    // always in [0,9]
            if ((unsigned)xi <= 3u) {
                float A = att * (cbx ? wxv : 1.0f - wxv) * (cby ? wyv : 1.0f - wyv);
                float2 f = *(const float2*)(feat_s + n * 16 + pairi * 2);
                float2* sp = (float2*)(Smine + (yi * 4 + xi) * 16 + pairi * 2);
                float2 sv = *sp;
                sv.x = fmaf(A, f.x, sv.x);
                sv.y = fmaf(A, f.y, sv.y);
                *sp = sv;
            }
            __syncwarp();   // order cross-lane smem RMW between iterations
        }
    }
    __syncthreads();

    // ---------- Phase C1: reduce 8 S copies ----------
    for (int e = tid; e < 640; e += 256) {
        float a = 0.f;
        #pragma unroll
        for (int c = 0; c < 8; ++c) a += S[c * 640 + e];
        Stot[e] = a;
    }
    __syncthreads();

    // ---------- Phase C2a: fold theta-wrap: Sfold[w][t][comp] ----------
    for (int e = tid; e < 512; e += 256) {
        int comp = e & 15;
        int t = (e >> 4) & 7;
        int w = e >> 7;
        float v = Stot[((t + 1) * 4 + w) * 16 + comp];     // h = t+1 (1..8)
        if (t == 7) v += Stot[(0 * 4 + w) * 16 + comp];    // h = 0
        if (t == 0) v += Stot[(9 * 4 + w) * 16 + comp];    // h = 9
        Sfold[e] = v;
    }
    __syncthreads();

    // ---------- Phase C2b: out[o,y] = sum kern[o,i,w,t,y,x] * Sfold[w,t,i,x] ----------
    // warp = o; lane = t*4 + y*2 + x  -> kern reads are 32 consecutive floats (coalesced)
    {
        const int t = lane >> 2;
        const int x = lane & 1;
        const float* kb = kern + warp * 1024;
        float acc = 0.f;
        #pragma unroll
        for (int i = 0; i < 8; ++i)
            #pragma unroll
            for (int w = 0; w < 4; ++w) {
                float kv = __ldg(kb + i * 128 + w * 32 + lane);
                float sv = Sfold[(w * 8 + t) * 16 + i * 2 + x];
                acc = fmaf(kv, sv, acc);
            }
        // reduce over x (bit0) and t (bits 2..4); keep y (bit1) distinct
        acc += __shfl_xor_sync(0xffffffffu, acc, 1);
        acc += __shfl_xor_sync(0xffffffffu, acc, 4);
        acc += __shfl_xor_sync(0xffffffffu, acc, 8);
        acc += __shfl_xor_sync(0xffffffffu, acc, 16);
        if ((lane & ~2u) == 0) {   // lanes 0 (y=0) and 2 (y=1)
            out[bm * 16 + warp * 2 + (lane >> 1)] = acc / shpsi[0];
        }
    }
}

extern "C" void kernel_launch(void* const* d_in, const int* in_sizes, int n_in,
                              void* d_out, int out_size)
{
    const float* field  = (const float*)d_in[0];
    const float* center = (const float*)d_in[1];
    const float* feat   = (const float*)d_in[2];
    const float* mask   = (const float*)d_in[3];
    const float* kern   = (const float*)d_in[4];
    float* out = (float*)d_out;

    cudaFuncSetAttribute(equi_cts_conv_kernel,
                         cudaFuncAttributeMaxDynamicSharedMemorySize, SMEM_BYTES);
    equi_cts_conv_kernel<<<B_ * M_, 256, SMEM_BYTES>>>(field, center, feat, mask, kern, out);
}

// round 9
// speedup vs baseline: 1.4009x; 1.0122x over previous
#include <cuda_runtime.h>
#include <math.h>

#define B_ 2
#define M_ 384
#define N_ 384

// Shared-memory layout (float offsets)
#define OFF_S     0        // 8 copies * 640 = 5120
#define OFF_CW    5120     // 384 * float4 corner weights = 1536
#define OFF_CPK   6656     // 384 ints (n<<8 | y0<<4 | (x0+1))
#define OFF_STOT  7040     // 640
#define OFF_SFOLD 7680     // 512  [w(4)][t(8)][comp(16)]
#define OFF_RED   8192     // 8 (psi warp partials)
#define OFF_PSI   8200     // 1
#define SMEM_FLOATS 8204
#define SMEM_BYTES  (SMEM_FLOATS * 4)   // 32816 B -> 6 blocks/SM

__global__ __launch_bounds__(256, 6)
void equi_cts_conv_kernel(const float* __restrict__ field,
                          const float* __restrict__ center,
                          const float* __restrict__ feat,
                          const float* __restrict__ mask,
                          const float* __restrict__ kern,
                          float* __restrict__ out)
{
    extern __shared__ float sm[];
    float*  S     = sm + OFF_S;
    float4* cw4   = (float4*)(sm + OFF_CW);
    int*    cpk   = (int*)(sm + OFF_CPK);
    float*  Stot  = sm + OFF_STOT;
    float*  Sfold = sm + OFF_SFOLD;
    float*  red   = sm + OFF_RED;
    float*  shpsi = sm + OFF_PSI;
    __shared__ int wcnt[16];

    const int tid  = threadIdx.x;
    const int lane = tid & 31;
    const int warp = tid >> 5;
    const int bm   = blockIdx.x;
    const int b    = bm / M_;

    const float cx = center[bm * 2 + 0];
    const float cy = center[bm * 2 + 1];

    // ---------- Phase 0: zero S copies ----------
    {
        float4 z = make_float4(0.f, 0.f, 0.f, 0.f);
        float4* S4 = (float4*)S;
        #pragma unroll
        for (int i = tid; i < 1280; i += 256) S4[i] = z;
    }

    // ---------- Phase A1: geometry + corner weights + ballots ----------
    float psi_part = 0.f;
    unsigned ballots[2];
    float4 a_cw[2];
    int    a_pk[2];
    bool   a_act[2];
    #pragma unroll
    for (int r = 0; r < 2; ++r) {
        int n = r * 256 + tid;
        bool act = false;
        float4 cwv = make_float4(0.f, 0.f, 0.f, 0.f);
        int pack = 0;
        if (n < N_) {
            float2 fp = *(const float2*)(field + ((size_t)b * N_ + n) * 2);
            float relx = (fp.x - cx) * (1.0f / 1.5f);
            float rely = (fp.y - cy) * (1.0f / 1.5f);
            float r2 = relx * relx + rely * rely;
            float s  = 1.0f - r2;
            if (s > 0.0f) {
                float att = s * s * s * mask[(size_t)b * N_ + n];
                float rr = sqrtf(r2 + 1e-9f);
                float theta = (relx == 0.0f && rely == 0.0f) ? 0.0f : atan2f(rely, relx);
                float ix = 4.0f * rr - 0.5f;                      // ((gx+1)*W-1)/2, W=4
                float gy = theta * 0.318309886183790672f * 0.8f;  // theta/pi * 8/10
                float iy = fmaf(5.0f, gy, 4.5f);                  // H=10
                float x0f = floorf(ix), y0f = floorf(iy);
                float wx = ix - x0f;
                float wy = iy - y0f;
                int x0 = (int)x0f, y0 = (int)y0f;                 // x0 in [-1,3], y0 in [0,8]
                float omx = 1.0f - wx, omy = 1.0f - wy;
                cwv.x = att * omx * omy;   // corner (0,0)
                cwv.y = att * wx  * omy;   // corner (1,0)
                cwv.z = att * omx * wy;    // corner (0,1)
                cwv.w = att * wx  * wy;    // corner (1,1)
                pack = ((x0 + 1) | (y0 << 4)) | (n << 8);
                psi_part += att;
                act = (att != 0.0f);
            }
        }
        a_cw[r] = cwv; a_pk[r] = pack; a_act[r] = act;
        ballots[r] = __ballot_sync(0xffffffffu, act);
        if (lane == 0) wcnt[r * 8 + warp] = __popc(ballots[r]);
    }

    // psi warp-reduce
    #pragma unroll
    for (int o = 16; o; o >>= 1) psi_part += __shfl_xor_sync(0xffffffffu, psi_part, o);
    if (lane == 0) red[warp] = psi_part;
    __syncthreads();   // covers S-zeroing, wcnt, red

    // ---------- Phase A2: deterministic prefix + compacted write ----------
    int nact;
    {
        int tot = 0, base0 = 0, base1 = 0;
        #pragma unroll
        for (int s2 = 0; s2 < 16; ++s2) {
            if (s2 == warp)     base0 = tot;
            if (s2 == warp + 8) base1 = tot;
            tot += wcnt[s2];
        }
        nact = tot;
        unsigned lt = (1u << lane) - 1u;
        if (a_act[0]) {
            int idx = base0 + __popc(ballots[0] & lt);
            cw4[idx] = a_cw[0]; cpk[idx] = a_pk[0];
        }
        if (a_act[1]) {
            int idx = base1 + __popc(ballots[1] & lt);
            cw4[idx] = a_cw[1]; cpk[idx] = a_pk[1];
        }
        if (tid == 0) {
            float p = 0.f;
            #pragma unroll
            for (int w = 0; w < 8; ++w) p += red[w];
            shpsi[0] = (p == 0.0f) ? 1.0f : p;
        }
    }
    __syncthreads();

    // ---------- Phase B: branchless scatter; one n per warp-iter ----------
    // lane = corner(2b) * 8 + pairi(3b); 32 lanes write 32 distinct smem addrs.
    // Straight-line predicated body -> lanes stay in one issue stream, so
    // cross-iteration smem RMW ordering holds without __syncwarp.
    {
        const int corner = lane >> 3;            // 0..3 = cby*2+cbx
        const int pairi  = lane & 7;
        const int cbx = corner & 1;
        const int cby = corner >> 1;
        float* Smine = S + warp * 640;
        const float* cwf = (const float*)cw4;
        const float* featB = feat + (size_t)b * N_ * 16;

        for (int k = warp; k < nact; k += 8) {
            float A  = cwf[k * 4 + corner];      // multicast LDS.32
            int   pk = cpk[k];                   // broadcast
            int xi = (pk & 15) - 1 + cbx;        // -1..4
            int yi = ((pk >> 4) & 15) + cby;     // 0..9
            bool ok = (unsigned)xi <= 3u;
            xi &= 3;                             // clamp; A zeroed when !ok
            A = ok ? A : 0.0f;
            int foff = ((pk >> 4) & ~15) + pairi * 2;   // n*16 + pairi*2
            float2 f = __ldg((const float2*)(featB + foff));
            float* sp = Smine + (yi * 4 + xi) * 16 + pairi * 2;
            float2 sv = *(float2*)sp;
            sv.x = fmaf(A, f.x, sv.x);
            sv.y = fmaf(A, f.y, sv.y);
            *(float2*)sp = sv;
        }
    }
    __syncthreads();

    // ---------- Phase C1: reduce 8 S copies ----------
    for (int e = tid; e < 640; e += 256) {
        float a = 0.f;
        #pragma unroll
        for (int c = 0; c < 8; ++c) a += S[c * 640 + e];
        Stot[e] = a;
    }
    __syncthreads();

    // ---------- Phase C2a: fold theta-wrap: Sfold[w][t][comp] ----------
    for (int e = tid; e < 512; e += 256) {
        int comp = e & 15;
        int t = (e >> 4) & 7;
        int w = e >> 7;
        float v = Stot[((t + 1) * 4 + w) * 16 + comp];     // h = t+1 (1..8)
        if (t == 7) v += Stot[(0 * 4 + w) * 16 + comp];    // h = 0
        if (t == 0) v += Stot[(9 * 4 + w) * 16 + comp];    // h = 9
        Sfold[e] = v;
    }
    __syncthreads();

    // ---------- Phase C2b: out[o,y] = sum kern[o,i,w,t,y,x] * Sfold[w,t,i,x] ----------
    // warp = o; lane = t*4 + y*2 + x -> kern reads fully coalesced, L1-resident
    {
        const int t = lane >> 2;
        const int x = lane & 1;
        const float* kb = kern + warp * 1024;
        float acc = 0.f;
        #pragma unroll
        for (int i = 0; i < 8; ++i)
            #pragma unroll
            for (int w = 0; w < 4; ++w) {
                float kv = __ldg(kb + i * 128 + w * 32 + lane);
                float sv = Sfold[(w * 8 + t) * 16 + i * 2 + x];
                acc = fmaf(kv, sv, acc);
            }
        // reduce over x (bit0) and t (bits 2..4); keep y (bit1) distinct
        acc += __shfl_xor_sync(0xffffffffu, acc, 1);
        acc += __shfl_xor_sync(0xffffffffu, acc, 4);
        acc += __shfl_xor_sync(0xffffffffu, acc, 8);
        acc += __shfl_xor_sync(0xffffffffu, acc, 16);
        if ((lane & ~2u) == 0) {   // lanes 0 (y=0) and 2 (y=1)
            out[bm * 16 + warp * 2 + (lane >> 1)] = acc / shpsi[0];
        }
    }
}

extern "C" void kernel_launch(void* const* d_in, const int* in_sizes, int n_in,
                              void* d_out, int out_size)
{
    const float* field  = (const float*)d_in[0];
    const float* center = (const float*)d_in[1];
    const float* feat   = (const float*)d_in[2];
    const float* mask   = (const float*)d_in[3];
    const float* kern   = (const float*)d_in[4];
    float* out = (float*)d_out;

    cudaFuncSetAttribute(equi_cts_conv_kernel,
                         cudaFuncAttributeMaxDynamicSharedMemorySize, SMEM_BYTES);
    equi_cts_conv_kernel<<<B_ * M_, 256, SMEM_BYTES>>>(field, center, feat, mask, kern, out);
}